// round 15
// baseline (speedup 1.0000x reference)
#include <cuda_runtime.h>
#include <cuda_bf16.h>
#include <cuda_fp16.h>
#include <cstdint>

#define NN      100000
#define IN_DIM  512
#define HIDDEN  128
#define NCLS    64
#define NEDGE   3200000

// ---------------- device scratch (allocation-free) ----------------
__device__ __half g_h16[(size_t)NN * HIDDEN];     // relu(X@W0), fp16
__device__ __half g_f16a[(size_t)NN * NCLS];      // dense out (fp16)
__device__ __half g_f16b[(size_t)NN * NCLS];      // after 1st spmm (fp16)
__device__ __nv_bfloat16 g_w0hi[IN_DIM * HIDDEN]; // W0^T as [n][k], hi part
__device__ __nv_bfloat16 g_w0lo[IN_DIM * HIDDEN]; // W0^T as [n][k], lo part
// CSR build
__device__ int2 g_edge[NEDGE];                    // packed (src, val-bits), sorted by dst
__device__ int  g_cnt[NN];
__device__ int  g_tmp[NN];
__device__ int  g_rp[NN + 1];
__device__ int  g_cur[NN];
__device__ int  g_bsum[512];
__device__ int  g_boff[512];

// ---------------------------------------------------------------------------
// W0 transpose + bf16 hi/lo split: [k][n] fp32 -> [n][k] bf16 x2.
// ---------------------------------------------------------------------------
__global__ void w0_conv(const float* __restrict__ W0)
{
    int i = blockIdx.x * 256 + threadIdx.x;     // i = n*512 + k
    int n = i >> 9;
    int k = i & 511;
    float v = W0[k * HIDDEN + n];
    __nv_bfloat16 hi = __float2bfloat16(v);
    g_w0hi[i] = hi;
    g_w0lo[i] = __float2bfloat16(v - __bfloat162float(hi));
}

// ---------------------------------------------------------------------------
// GEMM1 via tensor cores: H16 = fp16(relu(X @ W0))
// mma.sync.m16n8k16 bf16, hi/lo split, ldmatrix fragments.
// ---------------------------------------------------------------------------
#define ASTRIDE 40

__device__ __forceinline__ uint32_t pack_bf16x2(float a, float b)
{
    __nv_bfloat162 h = __floats2bfloat162_rn(a, b);
    return *(uint32_t*)&h;
}

__device__ __forceinline__ void mma16816(float* d, const uint32_t* a,
                                         uint32_t b0, uint32_t b1)
{
    asm("mma.sync.aligned.m16n8k16.row.col.f32.bf16.bf16.f32 "
        "{%0,%1,%2,%3}, {%4,%5,%6,%7}, {%8,%9}, {%0,%1,%2,%3};"
        : "+f"(d[0]), "+f"(d[1]), "+f"(d[2]), "+f"(d[3])
        : "r"(a[0]), "r"(a[1]), "r"(a[2]), "r"(a[3]), "r"(b0), "r"(b1));
}

__device__ __forceinline__ void ldsm_x4(uint32_t* r, uint32_t addr)
{
    asm volatile("ldmatrix.sync.aligned.m8n8.x4.shared.b16 {%0,%1,%2,%3}, [%4];"
                 : "=r"(r[0]), "=r"(r[1]), "=r"(r[2]), "=r"(r[3]) : "r"(addr));
}

__global__ __launch_bounds__(256)
void gemm1_mma(const float* __restrict__ X,
               const __nv_bfloat16* __restrict__ Whi,
               const __nv_bfloat16* __restrict__ Wlo,
               __half* __restrict__ H)
{
    __shared__ __nv_bfloat16 Ahi[128 * ASTRIDE];
    __shared__ __nv_bfloat16 Alo[128 * ASTRIDE];
    __shared__ __nv_bfloat16 Bhi[128 * ASTRIDE];
    __shared__ __nv_bfloat16 Blo[128 * ASTRIDE];

    const int tid    = threadIdx.x;
    const int lane   = tid & 31;
    const int wid    = tid >> 5;
    const int warp_m = wid >> 1;
    const int warp_n = wid & 1;
    const int bm     = blockIdx.x * 128;

    const int a_row = tid >> 1;
    const int a_kh  = (tid & 1) * 16;
    int grow = bm + a_row; if (grow >= NN) grow = NN - 1;
    const float* Xp = X + (size_t)grow * IN_DIM + a_kh;

    const int b_n = tid >> 1;
    const __nv_bfloat16* Whip = Whi + (size_t)b_n * IN_DIM + a_kh;
    const __nv_bfloat16* Wlop = Wlo + (size_t)b_n * IN_DIM + a_kh;

    // ldmatrix lane addresses (kt-invariant; kc adds 32 bytes)
    const int lrow = lane & 7;
    const int lm   = lane >> 3;
    const int a_ro = (lm & 1) * 8 + lrow;
    const int a_ko = (lm >> 1) * 8;
    const int b_no = (lm >> 1) * 8 + lrow;
    const int b_ko = (lm & 1) * 8;

    const uint32_t ahi_s = (uint32_t)__cvta_generic_to_shared(Ahi);
    const uint32_t alo_s = (uint32_t)__cvta_generic_to_shared(Alo);
    const uint32_t bhi_s = (uint32_t)__cvta_generic_to_shared(Bhi);
    const uint32_t blo_s = (uint32_t)__cvta_generic_to_shared(Blo);

    uint32_t aHiAd[2], aLoAd[2];
    #pragma unroll
    for (int mt = 0; mt < 2; mt++) {
        uint32_t off = ((warp_m * 32 + mt * 16 + a_ro) * ASTRIDE + a_ko) * 2;
        aHiAd[mt] = ahi_s + off;
        aLoAd[mt] = alo_s + off;
    }
    uint32_t bHiAd[4], bLoAd[4];
    #pragma unroll
    for (int p = 0; p < 4; p++) {
        uint32_t off = ((warp_n * 64 + p * 16 + b_no) * ASTRIDE + b_ko) * 2;
        bHiAd[p] = bhi_s + off;
        bLoAd[p] = blo_s + off;
    }

    float acc[2][8][4];
    #pragma unroll
    for (int mt = 0; mt < 2; mt++)
        #pragma unroll
        for (int nt = 0; nt < 8; nt++)
            #pragma unroll
            for (int j = 0; j < 4; j++) acc[mt][nt][j] = 0.f;

    float4 pa0 = *(const float4*)(Xp + 0);
    float4 pa1 = *(const float4*)(Xp + 4);
    float4 pa2 = *(const float4*)(Xp + 8);
    float4 pa3 = *(const float4*)(Xp + 12);
    uint4  pbh0 = *(const uint4*)(Whip + 0);
    uint4  pbh1 = *(const uint4*)(Whip + 8);
    uint4  pbl0 = *(const uint4*)(Wlop + 0);
    uint4  pbl1 = *(const uint4*)(Wlop + 8);

    const int NKT = IN_DIM / 32;   // 16
    for (int kt = 0; kt < NKT; kt++) {
        {
            float f[16] = {pa0.x, pa0.y, pa0.z, pa0.w, pa1.x, pa1.y, pa1.z, pa1.w,
                           pa2.x, pa2.y, pa2.z, pa2.w, pa3.x, pa3.y, pa3.z, pa3.w};
            float h[16], l[16];
            #pragma unroll
            for (int i = 0; i < 16; i++) {
                __nv_bfloat16 hb = __float2bfloat16(f[i]);
                h[i] = __bfloat162float(hb);
                l[i] = f[i] - h[i];
            }
            __nv_bfloat16* ah = &Ahi[a_row * ASTRIDE + a_kh];
            __nv_bfloat16* al = &Alo[a_row * ASTRIDE + a_kh];
            #pragma unroll
            for (int q = 0; q < 4; q++) {
                uint2 uh, ul;
                uh.x = pack_bf16x2(h[q*4+0], h[q*4+1]);
                uh.y = pack_bf16x2(h[q*4+2], h[q*4+3]);
                ul.x = pack_bf16x2(l[q*4+0], l[q*4+1]);
                ul.y = pack_bf16x2(l[q*4+2], l[q*4+3]);
                *(uint2*)(ah + q*4) = uh;
                *(uint2*)(al + q*4) = ul;
            }
        }
        {
            __nv_bfloat16* bh = &Bhi[b_n * ASTRIDE + a_kh];
            __nv_bfloat16* bl = &Blo[b_n * ASTRIDE + a_kh];
            *(uint4*)(bh + 0) = pbh0;
            *(uint4*)(bh + 8) = pbh1;
            *(uint4*)(bl + 0) = pbl0;
            *(uint4*)(bl + 8) = pbl1;
        }
        __syncthreads();

        if (kt + 1 < NKT) {
            const float* xn = Xp + (kt + 1) * 32;
            pa0 = *(const float4*)(xn + 0);
            pa1 = *(const float4*)(xn + 4);
            pa2 = *(const float4*)(xn + 8);
            pa3 = *(const float4*)(xn + 12);
            const __nv_bfloat16* whn = Whip + (kt + 1) * 32;
            const __nv_bfloat16* wln = Wlop + (kt + 1) * 32;
            pbh0 = *(const uint4*)(whn + 0);
            pbh1 = *(const uint4*)(whn + 8);
            pbl0 = *(const uint4*)(wln + 0);
            pbl1 = *(const uint4*)(wln + 8);
        }

        #pragma unroll
        for (int kc = 0; kc < 2; kc++) {
            const uint32_t kb = kc * 32;   // +16 halves
            uint32_t Afh[2][4], Afl[2][4];
            ldsm_x4(Afh[0], aHiAd[0] + kb);
            ldsm_x4(Afh[1], aHiAd[1] + kb);
            ldsm_x4(Afl[0], aLoAd[0] + kb);
            ldsm_x4(Afl[1], aLoAd[1] + kb);
            #pragma unroll
            for (int p = 0; p < 4; p++) {
                uint32_t bh[4], bl[4];
                ldsm_x4(bh, bHiAd[p] + kb);
                ldsm_x4(bl, bLoAd[p] + kb);
                #pragma unroll
                for (int mt = 0; mt < 2; mt++) {
                    mma16816(acc[mt][2*p],   Afh[mt], bh[0], bh[1]);
                    mma16816(acc[mt][2*p],   Afh[mt], bl[0], bl[1]);
                    mma16816(acc[mt][2*p],   Afl[mt], bh[0], bh[1]);
                    mma16816(acc[mt][2*p+1], Afh[mt], bh[2], bh[3]);
                    mma16816(acc[mt][2*p+1], Afh[mt], bl[2], bl[3]);
                    mma16816(acc[mt][2*p+1], Afl[mt], bh[2], bh[3]);
                }
            }
        }
        __syncthreads();
    }

    // epilogue: relu + fp16 store
    {
        const int g  = lane >> 2;
        const int tt = lane & 3;
        #pragma unroll
        for (int mt = 0; mt < 2; mt++) {
            #pragma unroll
            for (int nt = 0; nt < 8; nt++) {
                const int col = warp_n * 64 + nt * 8 + tt * 2;
                const int m0 = bm + warp_m * 32 + mt * 16 + g;
                if (m0 < NN) {
                    __half2 v = __floats2half2_rn(fmaxf(acc[mt][nt][0], 0.f),
                                                  fmaxf(acc[mt][nt][1], 0.f));
                    *(__half2*)&H[(size_t)m0 * HIDDEN + col] = v;
                }
                const int m1 = m0 + 8;
                if (m1 < NN) {
                    __half2 v = __floats2half2_rn(fmaxf(acc[mt][nt][2], 0.f),
                                                  fmaxf(acc[mt][nt][3], 0.f));
                    *(__half2*)&H[(size_t)m1 * HIDDEN + col] = v;
                }
            }
        }
    }
}

// ---------------------------------------------------------------------------
// GEMM2: O16 = fp16( H16[N,128] @ W1[128,64] ).
// ---------------------------------------------------------------------------
#define BM2 64
#define HT2_PITCH 132
#define G2_SMEM_FLOATS (HIDDEN * NCLS + BM2 * HT2_PITCH)
#define G2_SMEM_BYTES  (G2_SMEM_FLOATS * 4)

__global__ __launch_bounds__(256)
void gemm2(const __half* __restrict__ H16, const float* __restrict__ W1,
           __half* __restrict__ O16)
{
    extern __shared__ float sm2[];
    float* W1s = sm2;
    float* Hs  = sm2 + HIDDEN * NCLS;

    const int tid = threadIdx.x;
    const int bm  = blockIdx.x * BM2;

    {
        const float4* w1v = (const float4*)W1;
        float4* w1sv = (float4*)W1s;
        #pragma unroll
        for (int i = 0; i < 8; i++)
            w1sv[tid + i * 256] = w1v[tid + i * 256];
    }
    // load H tile: 64 rows x 128 halves = 1024 uint4 (8 halves each)
    #pragma unroll
    for (int j = 0; j < 4; j++) {
        int f = tid + j * 256;
        int row = f >> 4;          // 16 uint4 per row
        int q   = f & 15;          // halves [q*8, q*8+8)
        int gr = bm + row; if (gr >= NN) gr = NN - 1;
        uint4 v = *(const uint4*)&H16[(size_t)gr * HIDDEN + q * 8];
        const __half2* hp = (const __half2*)&v;
        float4 lo = {__low2float(hp[0]), __high2float(hp[0]),
                     __low2float(hp[1]), __high2float(hp[1])};
        float4 hi = {__low2float(hp[2]), __high2float(hp[2]),
                     __low2float(hp[3]), __high2float(hp[3])};
        *(float4*)&Hs[row * HT2_PITCH + q * 8]     = lo;
        *(float4*)&Hs[row * HT2_PITCH + q * 8 + 4] = hi;
    }
    __syncthreads();

    const int tr = tid >> 4;
    const int tc = tid & 15;
    const int r0 = tr * 4;
    const int c0 = tc * 4;

    float acc[4][4];
    #pragma unroll
    for (int i = 0; i < 4; i++)
        #pragma unroll
        for (int j = 0; j < 4; j++) acc[i][j] = 0.f;

    #pragma unroll 4
    for (int k = 0; k < HIDDEN; k += 4) {
        float4 a[4], b[4];
        #pragma unroll
        for (int i = 0; i < 4; i++)
            a[i] = *(const float4*)&Hs[(r0 + i) * HT2_PITCH + k];
        #pragma unroll
        for (int kk = 0; kk < 4; kk++)
            b[kk] = *(const float4*)&W1s[(k + kk) * NCLS + c0];
        #pragma unroll
        for (int i = 0; i < 4; i++) {
            acc[i][0] += a[i].x * b[0].x + a[i].y * b[1].x + a[i].z * b[2].x + a[i].w * b[3].x;
            acc[i][1] += a[i].x * b[0].y + a[i].y * b[1].y + a[i].z * b[2].y + a[i].w * b[3].y;
            acc[i][2] += a[i].x * b[0].z + a[i].y * b[1].z + a[i].z * b[2].z + a[i].w * b[3].z;
            acc[i][3] += a[i].x * b[0].w + a[i].y * b[1].w + a[i].z * b[2].w + a[i].w * b[3].w;
        }
    }

    #pragma unroll
    for (int i = 0; i < 4; i++) {
        const int m = bm + r0 + i;
        if (m < NN) {
            __half2 lo = __floats2half2_rn(acc[i][0], acc[i][1]);
            __half2 hi = __floats2half2_rn(acc[i][2], acc[i][3]);
            uint2 pk = {*(uint32_t*)&lo, *(uint32_t*)&hi};
            *(uint2*)&O16[(size_t)m * NCLS + c0] = pk;
        }
    }
}

// ---------------------------------------------------------------------------
// CSR build: counting sort of edges by dst, packed (src,val) payload.
// ---------------------------------------------------------------------------
__global__ void k_hist(const int* __restrict__ dst)
{
    int base = blockIdx.x * 1024 + threadIdx.x;
    #pragma unroll
    for (int j = 0; j < 4; j++) {
        int e = base + j * 256;
        if (e < NEDGE) atomicAdd(&g_cnt[dst[e]], 1);
    }
}

__global__ void k_scan_local()
{
    __shared__ int s[256];
    int t = threadIdx.x;
    int i = blockIdx.x * 256 + t;
    int v = (i < NN) ? g_cnt[i] : 0;
    s[t] = v;
    __syncthreads();
    int x = v;
    #pragma unroll
    for (int off = 1; off < 256; off <<= 1) {
        int y = (t >= off) ? s[t - off] : 0;
        __syncthreads();
        x += y;
        s[t] = x;
        __syncthreads();
    }
    if (i < NN) g_tmp[i] = x;
    if (t == 255) g_bsum[blockIdx.x] = x;
}

__global__ void k_scan_block(int nb)
{
    __shared__ int s[512];
    int t = threadIdx.x;
    int v = (t < nb) ? g_bsum[t] : 0;
    s[t] = v;
    __syncthreads();
    int x = v;
    #pragma unroll
    for (int off = 1; off < 512; off <<= 1) {
        int y = (t >= off) ? s[t - off] : 0;
        __syncthreads();
        x += y;
        s[t] = x;
        __syncthreads();
    }
    g_boff[t] = x - v;   // exclusive
}

__global__ void k_scan_final()
{
    int i = blockIdx.x * 256 + threadIdx.x;
    if (i < NN) {
        int e = g_tmp[i] - g_cnt[i] + g_boff[blockIdx.x];
        g_rp[i]  = e;
        g_cur[i] = e;
    }
    if (i == 0) g_rp[NN] = NEDGE;
}

__global__ void k_scatter(const int* __restrict__ src,
                          const int* __restrict__ dst,
                          const float* __restrict__ val)
{
    int base = blockIdx.x * 1024 + threadIdx.x;
    #pragma unroll
    for (int j = 0; j < 4; j++) {
        int e = base + j * 256;
        if (e < NEDGE) {
            int d = dst[e];
            int p = atomicAdd(&g_cur[d], 1);
            int2 pk;
            pk.x = src[e];
            pk.y = __float_as_int(val[e]);
            g_edge[p] = pk;
        }
    }
}

// ---------------------------------------------------------------------------
// CSR SpMM, fp16 gather / fp32 accumulate. One warp per dst row.
// Unroll-8 batches: 8 independent gathers in flight per lane.
// ---------------------------------------------------------------------------
template <bool OUT16>
__global__ __launch_bounds__(256)
void spmm_csr_f16(const __half* __restrict__ x, void* __restrict__ y)
{
    const int w    = (blockIdx.x * blockDim.x + threadIdx.x) >> 5;
    const int lane = threadIdx.x & 31;
    if (w >= NN) return;

    const int start = __ldg(&g_rp[w]);
    const int end   = __ldg(&g_rp[w + 1]);
    const __half2* xs = (const __half2*)x;   // row stride = 32 half2

    float2 acc = {0.f, 0.f};
    int e = start;

    for (; e + 8 <= end; e += 8) {
        int2 p[8];
        #pragma unroll
        for (int i = 0; i < 8; i++) p[i] = g_edge[e + i];
        float2 a[8];
        #pragma unroll
        for (int i = 0; i < 8; i++)
            a[i] = __half22float2(xs[(size_t)p[i].x * 32 + lane]);
        #pragma unroll
        for (int i = 0; i < 8; i++) {
            float v = __int_as_float(p[i].y);
            acc.x += v * a[i].x;
            acc.y += v * a[i].y;
        }
    }
    if (e + 4 <= end) {
        int2 p[4];
        #pragma unroll
        for (int i = 0; i < 4; i++) p[i] = g_edge[e + i];
        float2 a[4];
        #pragma unroll
        for (int i = 0; i < 4; i++)
            a[i] = __half22float2(xs[(size_t)p[i].x * 32 + lane]);
        #pragma unroll
        for (int i = 0; i < 4; i++) {
            float v = __int_as_float(p[i].y);
            acc.x += v * a[i].x;
            acc.y += v * a[i].y;
        }
        e += 4;
    }
    for (; e < end; e++) {
        int2 p = g_edge[e];
        float v = __int_as_float(p.y);
        float2 a = __half22float2(xs[(size_t)p.x * 32 + lane]);
        acc.x += v * a.x;
        acc.y += v * a.y;
    }

    if (OUT16) {
        ((__half2*)y)[(size_t)w * 32 + lane] = __floats2half2_rn(acc.x, acc.y);
    } else {
        ((float2*)y)[(size_t)w * 32 + lane] = acc;
    }
}

// ---------------------------------------------------------------------------
extern "C" void kernel_launch(void* const* d_in, const int* in_sizes, int n_in,
                              void* d_out, int out_size)
{
    const float* X  = (const float*)d_in[0];
    const float* W0 = (const float*)d_in[1];
    const float* W1 = (const float*)d_in[2];
    const float* ev = (const float*)d_in[3];
    const int*   es = (const int*)d_in[4];
    const int*   ed = (const int*)d_in[5];
    float* out = (float*)d_out;

    __half *h16, *f16a, *f16b;
    __nv_bfloat16 *whi, *wlo;
    int *cnt;
    cudaGetSymbolAddress((void**)&h16,  g_h16);
    cudaGetSymbolAddress((void**)&f16a, g_f16a);
    cudaGetSymbolAddress((void**)&f16b, g_f16b);
    cudaGetSymbolAddress((void**)&whi,  g_w0hi);
    cudaGetSymbolAddress((void**)&wlo,  g_w0lo);
    cudaGetSymbolAddress((void**)&cnt,  g_cnt);

    cudaFuncSetAttribute(gemm2, cudaFuncAttributeMaxDynamicSharedMemorySize,
                         G2_SMEM_BYTES);

    const int NB_SCAN = (NN + 255) / 256;          // 391
    const int EB      = (NEDGE + 1023) / 1024;     // 3125

    // CSR build first (independent of dense phase)
    cudaMemsetAsync(cnt, 0, NN * sizeof(int));
    k_hist<<<EB, 256>>>(ed);
    k_scan_local<<<NB_SCAN, 256>>>();
    k_scan_block<<<1, 512>>>(NB_SCAN);
    k_scan_final<<<NB_SCAN, 256>>>();
    k_scatter<<<EB, 256>>>(es, ed, ev);

    // dense phase
    w0_conv<<<(IN_DIM * HIDDEN) / 256, 256>>>(W0);
    gemm1_mma<<<(NN + 127) / 128, 256>>>(X, whi, wlo, h16);
    gemm2<<<(NN + BM2 - 1) / BM2, 256, G2_SMEM_BYTES>>>(h16, W1, f16a);

    // graph phase (fp16 gather, fp32 accumulate)
    const int CSR_GRID = (NN * 32 + 255) / 256;    // 12500
    spmm_csr_f16<true><<<CSR_GRID, 256>>>(f16a, f16b);
    spmm_csr_f16<false><<<CSR_GRID, 256>>>(f16b, out);
}

// round 16
// speedup vs baseline: 1.0286x; 1.0286x over previous
#include <cuda_runtime.h>
#include <cuda_bf16.h>
#include <cuda_fp16.h>
#include <cstdint>

#define NN      100000
#define IN_DIM  512
#define HIDDEN  128
#define NCLS    64
#define NEDGE   3200000

// ---------------- device scratch (allocation-free) ----------------
__device__ __half g_h16[(size_t)NN * HIDDEN];     // relu(X@W0), fp16
__device__ __half g_f16a[(size_t)NN * NCLS];      // dense out (fp16)
__device__ __half g_f16b[(size_t)NN * NCLS];      // after 1st spmm (fp16)
__device__ __nv_bfloat16 g_w0hi[IN_DIM * HIDDEN]; // W0^T as [n][k], hi part
__device__ __nv_bfloat16 g_w0lo[IN_DIM * HIDDEN]; // W0^T as [n][k], lo part
// CSR build
__device__ int2 g_edge[NEDGE];                    // packed (src, val-bits), sorted by dst
__device__ int  g_cnt[NN];
__device__ int  g_tmp[NN];
__device__ int  g_rp[NN + 1];
__device__ int  g_cur[NN];
__device__ int  g_bsum[512];
__device__ int  g_boff[512];

// ---------------------------------------------------------------------------
// W0 transpose + bf16 hi/lo split: [k][n] fp32 -> [n][k] bf16 x2.
// ---------------------------------------------------------------------------
__global__ void w0_conv(const float* __restrict__ W0)
{
    int i = blockIdx.x * 256 + threadIdx.x;     // i = n*512 + k
    int n = i >> 9;
    int k = i & 511;
    float v = W0[k * HIDDEN + n];
    __nv_bfloat16 hi = __float2bfloat16(v);
    g_w0hi[i] = hi;
    g_w0lo[i] = __float2bfloat16(v - __bfloat162float(hi));
}

// ---------------------------------------------------------------------------
// GEMM1 via tensor cores: H16 = fp16(relu(X @ W0))
// mma.sync.m16n8k16 bf16, hi/lo split, ldmatrix fragments.
// BK=16, 2-stage smem double buffer (48KB total), 1 barrier/iter:
// convert+store of tile kt+1 overlaps mma on tile kt.
// ---------------------------------------------------------------------------
#define AST2 24                        // halves per smem row (16 k + 8 pad)
#define STG  (128 * AST2)              // halves per array-stage = 3072
#define SBYT (STG * 2)                 // bytes per array-stage = 6144

__device__ __forceinline__ uint32_t pack_bf16x2(float a, float b)
{
    __nv_bfloat162 h = __floats2bfloat162_rn(a, b);
    return *(uint32_t*)&h;
}

__device__ __forceinline__ void mma16816(float* d, const uint32_t* a,
                                         uint32_t b0, uint32_t b1)
{
    asm("mma.sync.aligned.m16n8k16.row.col.f32.bf16.bf16.f32 "
        "{%0,%1,%2,%3}, {%4,%5,%6,%7}, {%8,%9}, {%0,%1,%2,%3};"
        : "+f"(d[0]), "+f"(d[1]), "+f"(d[2]), "+f"(d[3])
        : "r"(a[0]), "r"(a[1]), "r"(a[2]), "r"(a[3]), "r"(b0), "r"(b1));
}

__device__ __forceinline__ void ldsm_x4(uint32_t* r, uint32_t addr)
{
    asm volatile("ldmatrix.sync.aligned.m8n8.x4.shared.b16 {%0,%1,%2,%3}, [%4];"
                 : "=r"(r[0]), "=r"(r[1]), "=r"(r[2]), "=r"(r[3]) : "r"(addr));
}

__global__ __launch_bounds__(256, 2)
void gemm1_mma(const float* __restrict__ X,
               const __nv_bfloat16* __restrict__ Whi,
               const __nv_bfloat16* __restrict__ Wlo,
               __half* __restrict__ H)
{
    __shared__ __nv_bfloat16 SAhi[2 * STG];
    __shared__ __nv_bfloat16 SAlo[2 * STG];
    __shared__ __nv_bfloat16 SBhi[2 * STG];
    __shared__ __nv_bfloat16 SBlo[2 * STG];

    const int tid    = threadIdx.x;
    const int lane   = tid & 31;
    const int wid    = tid >> 5;
    const int warp_m = wid >> 1;
    const int warp_n = wid & 1;
    const int bm     = blockIdx.x * 128;

    // loaders: thread -> (row, k-half of 8)
    const int a_row = tid >> 1;
    const int a_kh  = (tid & 1) * 8;
    int grow = bm + a_row; if (grow >= NN) grow = NN - 1;
    const float* Xp = X + (size_t)grow * IN_DIM + a_kh;
    const __nv_bfloat16* Whip = Whi + (size_t)a_row * IN_DIM + a_kh;
    const __nv_bfloat16* Wlop = Wlo + (size_t)a_row * IN_DIM + a_kh;

    // ldmatrix lane offsets (stage-invariant)
    const int lrow = lane & 7;
    const int lm   = lane >> 3;
    const int a_ro = (lm & 1) * 8 + lrow;
    const int a_ko = (lm >> 1) * 8;
    const int b_no = (lm >> 1) * 8 + lrow;
    const int b_ko = (lm & 1) * 8;

    const uint32_t ahi_s = (uint32_t)__cvta_generic_to_shared(SAhi);
    const uint32_t alo_s = (uint32_t)__cvta_generic_to_shared(SAlo);
    const uint32_t bhi_s = (uint32_t)__cvta_generic_to_shared(SBhi);
    const uint32_t blo_s = (uint32_t)__cvta_generic_to_shared(SBlo);

    uint32_t offA[2], offB[4];
    #pragma unroll
    for (int mt = 0; mt < 2; mt++)
        offA[mt] = ((warp_m * 32 + mt * 16 + a_ro) * AST2 + a_ko) * 2;
    #pragma unroll
    for (int p = 0; p < 4; p++)
        offB[p] = ((warp_n * 64 + p * 16 + b_no) * AST2 + b_ko) * 2;

    // store offsets
    const uint32_t stA = (a_row * AST2 + a_kh);   // halves
    float acc[2][8][4];
    #pragma unroll
    for (int mt = 0; mt < 2; mt++)
        #pragma unroll
        for (int nt = 0; nt < 8; nt++)
            #pragma unroll
            for (int j = 0; j < 4; j++) acc[mt][nt][j] = 0.f;

    float4 pa0, pa1;
    uint4  pbh, pbl;

    // prologue: load + store tile 0 into stage 0
    pa0 = *(const float4*)(Xp + 0);
    pa1 = *(const float4*)(Xp + 4);
    pbh = *(const uint4*)(Whip);
    pbl = *(const uint4*)(Wlop);
    {
        float f[8] = {pa0.x, pa0.y, pa0.z, pa0.w, pa1.x, pa1.y, pa1.z, pa1.w};
        #pragma unroll
        for (int q = 0; q < 2; q++) {
            float h0 = __bfloat162float(__float2bfloat16(f[q*4+0]));
            float h1 = __bfloat162float(__float2bfloat16(f[q*4+1]));
            float h2 = __bfloat162float(__float2bfloat16(f[q*4+2]));
            float h3 = __bfloat162float(__float2bfloat16(f[q*4+3]));
            uint2 uh = {pack_bf16x2(h0, h1), pack_bf16x2(h2, h3)};
            uint2 ul = {pack_bf16x2(f[q*4+0]-h0, f[q*4+1]-h1),
                        pack_bf16x2(f[q*4+2]-h2, f[q*4+3]-h3)};
            *(uint2*)&SAhi[stA + q*4] = uh;
            *(uint2*)&SAlo[stA + q*4] = ul;
        }
        *(uint4*)&SBhi[stA] = pbh;
        *(uint4*)&SBlo[stA] = pbl;
    }
    __syncthreads();

    const int NKT = IN_DIM / 16;   // 32
    for (int kt = 0; kt < NKT; kt++) {
        const int cur = kt & 1;
        const uint32_t sb = cur * SBYT;

        // prefetch tile kt+1 (hidden under mma)
        if (kt + 1 < NKT) {
            const float* xn = Xp + (kt + 1) * 16;
            pa0 = *(const float4*)(xn + 0);
            pa1 = *(const float4*)(xn + 4);
            pbh = *(const uint4*)(Whip + (kt + 1) * 16);
            pbl = *(const uint4*)(Wlop + (kt + 1) * 16);
        }

        // mma on stage cur: 12 LDSM + 48 HMMA
        uint32_t Afh[2][4], Afl[2][4];
        ldsm_x4(Afh[0], ahi_s + sb + offA[0]);
        ldsm_x4(Afh[1], ahi_s + sb + offA[1]);
        ldsm_x4(Afl[0], alo_s + sb + offA[0]);
        ldsm_x4(Afl[1], alo_s + sb + offA[1]);
        #pragma unroll
        for (int p = 0; p < 4; p++) {
            uint32_t bh[4], bl[4];
            ldsm_x4(bh, bhi_s + sb + offB[p]);
            ldsm_x4(bl, blo_s + sb + offB[p]);
            #pragma unroll
            for (int mt = 0; mt < 2; mt++) {
                mma16816(acc[mt][2*p],   Afh[mt], bh[0], bh[1]);
                mma16816(acc[mt][2*p],   Afh[mt], bl[0], bl[1]);
                mma16816(acc[mt][2*p],   Afl[mt], bh[0], bh[1]);
                mma16816(acc[mt][2*p+1], Afh[mt], bh[2], bh[3]);
                mma16816(acc[mt][2*p+1], Afh[mt], bl[2], bl[3]);
                mma16816(acc[mt][2*p+1], Afl[mt], bh[2], bh[3]);
            }
        }

        // convert + store tile kt+1 into the other stage
        if (kt + 1 < NKT) {
            const uint32_t d = (cur ^ 1) * STG + stA;
            float f[8] = {pa0.x, pa0.y, pa0.z, pa0.w, pa1.x, pa1.y, pa1.z, pa1.w};
            #pragma unroll
            for (int q = 0; q < 2; q++) {
                float h0 = __bfloat162float(__float2bfloat16(f[q*4+0]));
                float h1 = __bfloat162float(__float2bfloat16(f[q*4+1]));
                float h2 = __bfloat162float(__float2bfloat16(f[q*4+2]));
                float h3 = __bfloat162float(__float2bfloat16(f[q*4+3]));
                uint2 uh = {pack_bf16x2(h0, h1), pack_bf16x2(h2, h3)};
                uint2 ul = {pack_bf16x2(f[q*4+0]-h0, f[q*4+1]-h1),
                            pack_bf16x2(f[q*4+2]-h2, f[q*4+3]-h3)};
                *(uint2*)&SAhi[d + q*4] = uh;
                *(uint2*)&SAlo[d + q*4] = ul;
            }
            *(uint4*)&SBhi[d] = pbh;
            *(uint4*)&SBlo[d] = pbl;
        }
        __syncthreads();
    }

    // epilogue: relu + fp16 store
    {
        const int g  = lane >> 2;
        const int tt = lane & 3;
        #pragma unroll
        for (int mt = 0; mt < 2; mt++) {
            #pragma unroll
            for (int nt = 0; nt < 8; nt++) {
                const int col = warp_n * 64 + nt * 8 + tt * 2;
                const int m0 = bm + warp_m * 32 + mt * 16 + g;
                if (m0 < NN) {
                    __half2 v = __floats2half2_rn(fmaxf(acc[mt][nt][0], 0.f),
                                                  fmaxf(acc[mt][nt][1], 0.f));
                    *(__half2*)&H[(size_t)m0 * HIDDEN + col] = v;
                }
                const int m1 = m0 + 8;
                if (m1 < NN) {
                    __half2 v = __floats2half2_rn(fmaxf(acc[mt][nt][2], 0.f),
                                                  fmaxf(acc[mt][nt][3], 0.f));
                    *(__half2*)&H[(size_t)m1 * HIDDEN + col] = v;
                }
            }
        }
    }
}

// ---------------------------------------------------------------------------
// GEMM2: O16 = fp16( H16[N,128] @ W1[128,64] ).
// ---------------------------------------------------------------------------
#define BM2 64
#define HT2_PITCH 132
#define G2_SMEM_FLOATS (HIDDEN * NCLS + BM2 * HT2_PITCH)
#define G2_SMEM_BYTES  (G2_SMEM_FLOATS * 4)

__global__ __launch_bounds__(256)
void gemm2(const __half* __restrict__ H16, const float* __restrict__ W1,
           __half* __restrict__ O16)
{
    extern __shared__ float sm2[];
    float* W1s = sm2;
    float* Hs  = sm2 + HIDDEN * NCLS;

    const int tid = threadIdx.x;
    const int bm  = blockIdx.x * BM2;

    {
        const float4* w1v = (const float4*)W1;
        float4* w1sv = (float4*)W1s;
        #pragma unroll
        for (int i = 0; i < 8; i++)
            w1sv[tid + i * 256] = w1v[tid + i * 256];
    }
    #pragma unroll
    for (int j = 0; j < 4; j++) {
        int f = tid + j * 256;
        int row = f >> 4;
        int q   = f & 15;
        int gr = bm + row; if (gr >= NN) gr = NN - 1;
        uint4 v = *(const uint4*)&H16[(size_t)gr * HIDDEN + q * 8];
        const __half2* hp = (const __half2*)&v;
        float4 lo = {__low2float(hp[0]), __high2float(hp[0]),
                     __low2float(hp[1]), __high2float(hp[1])};
        float4 hi = {__low2float(hp[2]), __high2float(hp[2]),
                     __low2float(hp[3]), __high2float(hp[3])};
        *(float4*)&Hs[row * HT2_PITCH + q * 8]     = lo;
        *(float4*)&Hs[row * HT2_PITCH + q * 8 + 4] = hi;
    }
    __syncthreads();

    const int tr = tid >> 4;
    const int tc = tid & 15;
    const int r0 = tr * 4;
    const int c0 = tc * 4;

    float acc[4][4];
    #pragma unroll
    for (int i = 0; i < 4; i++)
        #pragma unroll
        for (int j = 0; j < 4; j++) acc[i][j] = 0.f;

    #pragma unroll 4
    for (int k = 0; k < HIDDEN; k += 4) {
        float4 a[4], b[4];
        #pragma unroll
        for (int i = 0; i < 4; i++)
            a[i] = *(const float4*)&Hs[(r0 + i) * HT2_PITCH + k];
        #pragma unroll
        for (int kk = 0; kk < 4; kk++)
            b[kk] = *(const float4*)&W1s[(k + kk) * NCLS + c0];
        #pragma unroll
        for (int i = 0; i < 4; i++) {
            acc[i][0] += a[i].x * b[0].x + a[i].y * b[1].x + a[i].z * b[2].x + a[i].w * b[3].x;
            acc[i][1] += a[i].x * b[0].y + a[i].y * b[1].y + a[i].z * b[2].y + a[i].w * b[3].y;
            acc[i][2] += a[i].x * b[0].z + a[i].y * b[1].z + a[i].z * b[2].z + a[i].w * b[3].z;
            acc[i][3] += a[i].x * b[0].w + a[i].y * b[1].w + a[i].z * b[2].w + a[i].w * b[3].w;
        }
    }

    #pragma unroll
    for (int i = 0; i < 4; i++) {
        const int m = bm + r0 + i;
        if (m < NN) {
            __half2 lo = __floats2half2_rn(acc[i][0], acc[i][1]);
            __half2 hi = __floats2half2_rn(acc[i][2], acc[i][3]);
            uint2 pk = {*(uint32_t*)&lo, *(uint32_t*)&hi};
            *(uint2*)&O16[(size_t)m * NCLS + c0] = pk;
        }
    }
}

// ---------------------------------------------------------------------------
// CSR build: counting sort of edges by dst, packed (src,val) payload.
// ---------------------------------------------------------------------------
__global__ void k_hist(const int* __restrict__ dst)
{
    int base = blockIdx.x * 1024 + threadIdx.x;
    #pragma unroll
    for (int j = 0; j < 4; j++) {
        int e = base + j * 256;
        if (e < NEDGE) atomicAdd(&g_cnt[dst[e]], 1);
    }
}

__global__ void k_scan_local()
{
    __shared__ int s[256];
    int t = threadIdx.x;
    int i = blockIdx.x * 256 + t;
    int v = (i < NN) ? g_cnt[i] : 0;
    s[t] = v;
    __syncthreads();
    int x = v;
    #pragma unroll
    for (int off = 1; off < 256; off <<= 1) {
        int y = (t >= off) ? s[t - off] : 0;
        __syncthreads();
        x += y;
        s[t] = x;
        __syncthreads();
    }
    if (i < NN) g_tmp[i] = x;
    if (t == 255) g_bsum[blockIdx.x] = x;
}

__global__ void k_scan_block(int nb)
{
    __shared__ int s[512];
    int t = threadIdx.x;
    int v = (t < nb) ? g_bsum[t] : 0;
    s[t] = v;
    __syncthreads();
    int x = v;
    #pragma unroll
    for (int off = 1; off < 512; off <<= 1) {
        int y = (t >= off) ? s[t - off] : 0;
        __syncthreads();
        x += y;
        s[t] = x;
        __syncthreads();
    }
    g_boff[t] = x - v;   // exclusive
}

__global__ void k_scan_final()
{
    int i = blockIdx.x * 256 + threadIdx.x;
    if (i < NN) {
        int e = g_tmp[i] - g_cnt[i] + g_boff[blockIdx.x];
        g_rp[i]  = e;
        g_cur[i] = e;
    }
    if (i == 0) g_rp[NN] = NEDGE;
}

__global__ void k_scatter(const int* __restrict__ src,
                          const int* __restrict__ dst,
                          const float* __restrict__ val)
{
    int base = blockIdx.x * 1024 + threadIdx.x;
    #pragma unroll
    for (int j = 0; j < 4; j++) {
        int e = base + j * 256;
        if (e < NEDGE) {
            int d = dst[e];
            int p = atomicAdd(&g_cur[d], 1);
            int2 pk;
            pk.x = src[e];
            pk.y = __float_as_int(val[e]);
            g_edge[p] = pk;
        }
    }
}

// ---------------------------------------------------------------------------
// CSR SpMM, fp16 gather / fp32 accumulate. One warp per dst row.
// ---------------------------------------------------------------------------
template <bool OUT16>
__global__ __launch_bounds__(256)
void spmm_csr_f16(const __half* __restrict__ x, void* __restrict__ y)
{
    const int w    = (blockIdx.x * blockDim.x + threadIdx.x) >> 5;
    const int lane = threadIdx.x & 31;
    if (w >= NN) return;

    const int start = __ldg(&g_rp[w]);
    const int end   = __ldg(&g_rp[w + 1]);
    const __half2* xs = (const __half2*)x;   // row stride = 32 half2

    float2 acc = {0.f, 0.f};
    int e = start;

    for (; e + 8 <= end; e += 8) {
        int2 p[8];
        #pragma unroll
        for (int i = 0; i < 8; i++) p[i] = g_edge[e + i];
        float2 a[8];
        #pragma unroll
        for (int i = 0; i < 8; i++)
            a[i] = __half22float2(xs[(size_t)p[i].x * 32 + lane]);
        #pragma unroll
        for (int i = 0; i < 8; i++) {
            float v = __int_as_float(p[i].y);
            acc.x += v * a[i].x;
            acc.y += v * a[i].y;
        }
    }
    if (e + 4 <= end) {
        int2 p[4];
        #pragma unroll
        for (int i = 0; i < 4; i++) p[i] = g_edge[e + i];
        float2 a[4];
        #pragma unroll
        for (int i = 0; i < 4; i++)
            a[i] = __half22float2(xs[(size_t)p[i].x * 32 + lane]);
        #pragma unroll
        for (int i = 0; i < 4; i++) {
            float v = __int_as_float(p[i].y);
            acc.x += v * a[i].x;
            acc.y += v * a[i].y;
        }
        e += 4;
    }
    for (; e < end; e++) {
        int2 p = g_edge[e];
        float v = __int_as_float(p.y);
        float2 a = __half22float2(xs[(size_t)p.x * 32 + lane]);
        acc.x += v * a.x;
        acc.y += v * a.y;
    }

    if (OUT16) {
        ((__half2*)y)[(size_t)w * 32 + lane] = __floats2half2_rn(acc.x, acc.y);
    } else {
        ((float2*)y)[(size_t)w * 32 + lane] = acc;
    }
}

// ---------------------------------------------------------------------------
extern "C" void kernel_launch(void* const* d_in, const int* in_sizes, int n_in,
                              void* d_out, int out_size)
{
    const float* X  = (const float*)d_in[0];
    const float* W0 = (const float*)d_in[1];
    const float* W1 = (const float*)d_in[2];
    const float* ev = (const float*)d_in[3];
    const int*   es = (const int*)d_in[4];
    const int*   ed = (const int*)d_in[5];
    float* out = (float*)d_out;

    __half *h16, *f16a, *f16b;
    __nv_bfloat16 *whi, *wlo;
    int *cnt;
    cudaGetSymbolAddress((void**)&h16,  g_h16);
    cudaGetSymbolAddress((void**)&f16a, g_f16a);
    cudaGetSymbolAddress((void**)&f16b, g_f16b);
    cudaGetSymbolAddress((void**)&whi,  g_w0hi);
    cudaGetSymbolAddress((void**)&wlo,  g_w0lo);
    cudaGetSymbolAddress((void**)&cnt,  g_cnt);

    cudaFuncSetAttribute(gemm2, cudaFuncAttributeMaxDynamicSharedMemorySize,
                         G2_SMEM_BYTES);

    const int NB_SCAN = (NN + 255) / 256;          // 391
    const int EB      = (NEDGE + 1023) / 1024;     // 3125

    // dense phase first
    cudaMemsetAsync(cnt, 0, NN * sizeof(int));
    w0_conv<<<(IN_DIM * HIDDEN) / 256, 256>>>(W0);
    gemm1_mma<<<(NN + 127) / 128, 256>>>(X, whi, wlo, h16);
    gemm2<<<(NN + BM2 - 1) / BM2, 256, G2_SMEM_BYTES>>>(h16, W1, f16a);

    // CSR build
    k_hist<<<EB, 256>>>(ed);
    k_scan_local<<<NB_SCAN, 256>>>();
    k_scan_block<<<1, 512>>>(NB_SCAN);
    k_scan_final<<<NB_SCAN, 256>>>();
    k_scatter<<<EB, 256>>>(es, ed, ev);

    // graph phase (fp16 gather, fp32 accumulate)
    const int CSR_GRID = (NN * 32 + 255) / 256;    // 12500
    spmm_csr_f16<true><<<CSR_GRID, 256>>>(f16a, f16b);
    spmm_csr_f16<false><<<CSR_GRID, 256>>>(f16b, out);
}